// round 1
// baseline (speedup 1.0000x reference)
#include <cuda_runtime.h>
#include <math.h>

#define Bsz 1024
#define Ssz 350
#define Vsz 41
#define H0 256
#define H1 128
#define H2 32
#define LAT 512
#define BT 8
#define NCTA 128
#define NTHR 256

// ---------------- persistent device scratch (no allocations allowed) ----------------
__device__ float4 g_Whh0p[64 * 768];    // Whh0 packed: [kc][j] = W[j][4kc..4kc+3]
__device__ float4 g_Wih1p[64 * 384];
__device__ float4 g_Whh1p[32 * 384];
__device__ float4 g_Wih2p[32 * 96];
__device__ float4 g_Whh2p[8 * 96];
__device__ float4 g_Wih0p[128 * 768];   // for G0 precompute
__device__ float4 g_Winitp[128 * 416];  // for Hinit precompute
__device__ float  g_WprojT[H2 * Vsz];   // [k][j]
__device__ float  g_G0[Vsz * 768];      // G0[v][j] = (Wih0 @ emb[v])_j + bih0_j
__device__ float  g_Hinit[Bsz * 416];   // initial h states

// ---------------- math helpers ----------------
__device__ __forceinline__ float sigf(float x) {
    // 1/(1+exp(-x)); safe at +/-inf
    return __fdividef(1.0f, 1.0f + __expf(-x));
}
__device__ __forceinline__ float tanh_(float x) {
    // sign-symmetric, overflow-safe tanh via exp
    float ax = fabsf(x);
    float e = __expf(-2.0f * ax);            // in (0,1]
    float t = __fdividef(1.0f - e, 1.0f + e);
    return copysignf(t, x);
}

// ---------------- prep kernels ----------------
__global__ void k_pack4(int which, const float* __restrict__ src, int OUT, int IN) {
    float4* dst;
    switch (which) {
        case 0: dst = g_Whh0p; break;
        case 1: dst = g_Wih1p; break;
        case 2: dst = g_Whh1p; break;
        case 3: dst = g_Wih2p; break;
        case 4: dst = g_Whh2p; break;
        case 5: dst = g_Wih0p; break;
        default: dst = g_Winitp; break;
    }
    int total = OUT * (IN >> 2);
    for (int idx = blockIdx.x * blockDim.x + threadIdx.x; idx < total;
         idx += gridDim.x * blockDim.x) {
        int kc = idx / OUT, j = idx - kc * OUT;
        const float* s = src + (size_t)j * IN + 4 * kc;
        dst[idx] = make_float4(s[0], s[1], s[2], s[3]);
    }
}

__global__ void k_wproj(const float* __restrict__ Wproj) {
    for (int i = threadIdx.x; i < H2 * Vsz; i += blockDim.x) {
        int k = i / Vsz, j = i - k * Vsz;
        g_WprojT[i] = Wproj[j * H2 + k];
    }
}

// G0[v][j] = bih0[j] + sum_k Wih0[j][k] * (W_emb[k][v] + b_emb[k])
__global__ void k_g0(const float* __restrict__ W_emb, const float* __restrict__ b_emb,
                     const float* __restrict__ bih0) {
    int v = blockIdx.x;     // 41 blocks
    int j = threadIdx.x;    // 768 threads
    float acc = bih0[j];
    for (int kc = 0; kc < 128; kc++) {
        float w[4];
        *(float4*)w = g_Wih0p[kc * 768 + j];
#pragma unroll
        for (int c = 0; c < 4; c++) {
            int k = 4 * kc + c;
            acc += w[c] * (W_emb[k * Vsz + v] + b_emb[k]);
        }
    }
    g_G0[v * 768 + j] = acc;
}

// Hinit[b][c] = b_init[c] + sum_k latent[b][k] * W_init[c][k]
__global__ void k_hinit(const float* __restrict__ latent, const float* __restrict__ b_init) {
    __shared__ float lat[8 * 512];
    int b0 = blockIdx.x * 8;    // 128 blocks
    for (int idx = threadIdx.x; idx < 8 * 512; idx += blockDim.x)
        lat[idx] = latent[(size_t)b0 * 512 + idx];
    __syncthreads();
    int c = threadIdx.x;        // 416 threads
    float acc[8];
    float bi = b_init[c];
#pragma unroll
    for (int r = 0; r < 8; r++) acc[r] = bi;
    for (int kc = 0; kc < 128; kc++) {
        float w[4];
        *(float4*)w = g_Winitp[kc * 416 + c];
#pragma unroll
        for (int c4 = 0; c4 < 4; c4++) {
            float wv = w[c4];
            int k = 4 * kc + c4;
#pragma unroll
            for (int r = 0; r < 8; r++) acc[r] += wv * lat[r * 512 + k];
        }
    }
#pragma unroll
    for (int r = 0; r < 8; r++) g_Hinit[(size_t)(b0 + r) * 416 + c] = acc[r];
}

// ---------------- main persistent GRU kernel ----------------
__global__ __launch_bounds__(NTHR, 1)
void k_main(const int* __restrict__ tokens,
            const float* __restrict__ bhh0,
            const float* __restrict__ bih1, const float* __restrict__ bhh1,
            const float* __restrict__ bih2, const float* __restrict__ bhh2,
            const float* __restrict__ b_proj,
            float* __restrict__ out, float* __restrict__ pred) {
    // h stored transposed: h{L}t[dim][row], row minor (8 rows, 32B stride -> float4 per 4 rows)
    __shared__ __align__(16) float h0t[H0 * BT];
    __shared__ __align__(16) float h1t[H1 * BT];
    __shared__ __align__(16) float h2t[H2 * BT];
    __shared__ float lg[BT][44];
    __shared__ int toks_s[BT];

    const int tid = threadIdx.x;
    const int b0 = blockIdx.x * BT;

    // load initial state (transposed into smem)
    for (int idx = tid; idx < BT * 416; idx += NTHR) {
        int row = idx / 416, c = idx - row * 416;
        float v = g_Hinit[(size_t)(b0 + row) * 416 + c];
        if (c < H0)            h0t[c * BT + row] = v;
        else if (c < H0 + H1)  h1t[(c - H0) * BT + row] = v;
        else                   h2t[(c - (H0 + H1)) * BT + row] = v;
    }

    const int jj = tid & 127;    // phase A/B column
    const int rh = tid >> 7;     // row half
    const int r0 = rh * 4;
    const int jc = tid & 31;     // phase C column
    const int rowC = tid >> 5;   // phase C row

    // bias preload (stay in registers across all 350 steps)
    const float bh0r = bhh0[jj],        bh0r2 = bhh0[jj + 128];
    const float bh0z = bhh0[256 + jj],  bh0z2 = bhh0[384 + jj];
    const float bh0n = bhh0[512 + jj],  bh0n2 = bhh0[640 + jj];
    const float b1r = bih1[jj] + bhh1[jj];
    const float b1z = bih1[128 + jj] + bhh1[128 + jj];
    const float b1in = bih1[256 + jj];
    const float b1hn = bhh1[256 + jj];
    const float b2r = bih2[jc] + bhh2[jc];
    const float b2z = bih2[32 + jc] + bhh2[32 + jc];
    const float b2in = bih2[64 + jc];
    const float b2hn = bhh2[64 + jc];

    __syncthreads();

    for (int st = 0; st < Ssz; st++) {
        if (tid < BT) toks_s[tid] = (st == 0) ? 1 : tokens[(size_t)(b0 + tid) * Ssz + st];
        __syncthreads();

        // ======== Phase A: layer-0 GRU (x via G0 table, gh0 = h0 @ Whh0^T) ========
        float ar[2][4], az[2][4], an[2][4], gin[2][4];
        {
            int tk[4];
#pragma unroll
            for (int r = 0; r < 4; r++) tk[r] = toks_s[r0 + r];
#pragma unroll
            for (int e = 0; e < 2; e++) {
                int j = jj + 128 * e;
                float br = e ? bh0r2 : bh0r;
                float bz = e ? bh0z2 : bh0z;
                float bn = e ? bh0n2 : bh0n;
#pragma unroll
                for (int r = 0; r < 4; r++) {
                    const float* g = g_G0 + tk[r] * 768;
                    ar[e][r] = br + g[j];
                    az[e][r] = bz + g[256 + j];
                    gin[e][r] = g[512 + j];
                    an[e][r] = bn;
                }
            }
        }
        for (int kc = 0; kc < 64; kc++) {
            float wr[2][4], wz[2][4], wn[2][4], hv[4][4];
            *(float4*)wr[0] = g_Whh0p[kc * 768 + jj];
            *(float4*)wr[1] = g_Whh0p[kc * 768 + 128 + jj];
            *(float4*)wz[0] = g_Whh0p[kc * 768 + 256 + jj];
            *(float4*)wz[1] = g_Whh0p[kc * 768 + 384 + jj];
            *(float4*)wn[0] = g_Whh0p[kc * 768 + 512 + jj];
            *(float4*)wn[1] = g_Whh0p[kc * 768 + 640 + jj];
#pragma unroll
            for (int c = 0; c < 4; c++)
                *(float4*)hv[c] = *(const float4*)(h0t + (kc * 4 + c) * BT + r0);
#pragma unroll
            for (int c = 0; c < 4; c++)
#pragma unroll
                for (int r = 0; r < 4; r++) {
                    float h = hv[c][r];
                    ar[0][r] += wr[0][c] * h; ar[1][r] += wr[1][c] * h;
                    az[0][r] += wz[0][c] * h; az[1][r] += wz[1][c] * h;
                    an[0][r] += wn[0][c] * h; an[1][r] += wn[1][c] * h;
                }
        }
        __syncthreads();
#pragma unroll
        for (int e = 0; e < 2; e++) {
            int j = jj + 128 * e;
            float hn4[4];
#pragma unroll
            for (int r = 0; r < 4; r++) {
                float hold = h0t[j * BT + r0 + r];
                float rg = sigf(ar[e][r]);
                float zg = sigf(az[e][r]);
                float ng = tanh_(gin[e][r] + rg * an[e][r]);
                hn4[r] = (1.0f - zg) * ng + zg * hold;
            }
            *(float4*)(h0t + j * BT + r0) = make_float4(hn4[0], hn4[1], hn4[2], hn4[3]);
        }
        __syncthreads();

        // ======== Phase B: layer-1 GRU (gi1 over new h0, gh1 over old h1) ========
        float a_r[4], a_z[4], a_i[4], a_h[4];
#pragma unroll
        for (int r = 0; r < 4; r++) { a_r[r] = b1r; a_z[r] = b1z; a_i[r] = b1in; a_h[r] = b1hn; }
        for (int kc = 0; kc < 64; kc++) {
            float w0[4], w1[4], w2[4], hv[4][4];
            *(float4*)w0 = g_Wih1p[kc * 384 + jj];
            *(float4*)w1 = g_Wih1p[kc * 384 + 128 + jj];
            *(float4*)w2 = g_Wih1p[kc * 384 + 256 + jj];
#pragma unroll
            for (int c = 0; c < 4; c++)
                *(float4*)hv[c] = *(const float4*)(h0t + (kc * 4 + c) * BT + r0);
#pragma unroll
            for (int c = 0; c < 4; c++)
#pragma unroll
                for (int r = 0; r < 4; r++) {
                    float h = hv[c][r];
                    a_r[r] += w0[c] * h; a_z[r] += w1[c] * h; a_i[r] += w2[c] * h;
                }
        }
        for (int kc = 0; kc < 32; kc++) {
            float w0[4], w1[4], w2[4], hv[4][4];
            *(float4*)w0 = g_Whh1p[kc * 384 + jj];
            *(float4*)w1 = g_Whh1p[kc * 384 + 128 + jj];
            *(float4*)w2 = g_Whh1p[kc * 384 + 256 + jj];
#pragma unroll
            for (int c = 0; c < 4; c++)
                *(float4*)hv[c] = *(const float4*)(h1t + (kc * 4 + c) * BT + r0);
#pragma unroll
            for (int c = 0; c < 4; c++)
#pragma unroll
                for (int r = 0; r < 4; r++) {
                    float h = hv[c][r];
                    a_r[r] += w0[c] * h; a_z[r] += w1[c] * h; a_h[r] += w2[c] * h;
                }
        }
        __syncthreads();
        {
            float hn4[4];
#pragma unroll
            for (int r = 0; r < 4; r++) {
                float hold = h1t[jj * BT + r0 + r];
                float rg = sigf(a_r[r]);
                float zg = sigf(a_z[r]);
                float ng = tanh_(a_i[r] + rg * a_h[r]);
                hn4[r] = (1.0f - zg) * ng + zg * hold;
            }
            *(float4*)(h1t + jj * BT + r0) = make_float4(hn4[0], hn4[1], hn4[2], hn4[3]);
        }
        __syncthreads();

        // ======== Phase C: layer-2 GRU (gi2 over new h1, gh2 over old h2) ========
        float c_r = b2r, c_z = b2z, c_i = b2in, c_h = b2hn;
        for (int kc = 0; kc < 32; kc++) {
            float w0[4], w1[4], w2[4];
            *(float4*)w0 = g_Wih2p[kc * 96 + jc];
            *(float4*)w1 = g_Wih2p[kc * 96 + 32 + jc];
            *(float4*)w2 = g_Wih2p[kc * 96 + 64 + jc];
#pragma unroll
            for (int c = 0; c < 4; c++) {
                float h = h1t[(kc * 4 + c) * BT + rowC];
                c_r += w0[c] * h; c_z += w1[c] * h; c_i += w2[c] * h;
            }
        }
        for (int kc = 0; kc < 8; kc++) {
            float w0[4], w1[4], w2[4];
            *(float4*)w0 = g_Whh2p[kc * 96 + jc];
            *(float4*)w1 = g_Whh2p[kc * 96 + 32 + jc];
            *(float4*)w2 = g_Whh2p[kc * 96 + 64 + jc];
#pragma unroll
            for (int c = 0; c < 4; c++) {
                float h = h2t[(kc * 4 + c) * BT + rowC];
                c_r += w0[c] * h; c_z += w1[c] * h; c_h += w2[c] * h;
            }
        }
        __syncthreads();
        {
            float hold = h2t[jc * BT + rowC];
            float rg = sigf(c_r);
            float zg = sigf(c_z);
            float ng = tanh_(c_i + rg * c_h);
            h2t[jc * BT + rowC] = (1.0f - zg) * ng + zg * hold;
        }
        __syncthreads();

        // ======== Phase D: projection logits + argmax ========
        for (int idx = tid; idx < BT * Vsz; idx += NTHR) {
            int row = idx / Vsz, j = idx - row * Vsz;
            float acc = b_proj[j];
#pragma unroll
            for (int k = 0; k < H2; k++)
                acc += g_WprojT[k * Vsz + j] * h2t[k * BT + row];
            out[((size_t)(b0 + row) * Ssz + st) * Vsz + j] = acc;
            lg[row][j] = acc;
        }
        __syncthreads();
        if (tid < BT && pred) {
            float best = lg[tid][0];
            int bi = 0;
#pragma unroll 1
            for (int j = 1; j < Vsz; j++) {
                float v = lg[tid][j];
                if (v > best) { best = v; bi = j; }
            }
            pred[(size_t)(b0 + tid) * Ssz + st] = (float)bi;
        }
        __syncthreads();
    }
}

// ---------------- launch ----------------
extern "C" void kernel_launch(void* const* d_in, const int* in_sizes, int n_in,
                              void* d_out, int out_size) {
    const float* latent  = (const float*)d_in[0];
    const int*   tokens  = (const int*)d_in[1];
    const float* W_emb   = (const float*)d_in[2];
    const float* b_emb   = (const float*)d_in[3];
    const float* W_init  = (const float*)d_in[4];
    const float* b_init  = (const float*)d_in[5];
    const float* Wih0    = (const float*)d_in[6];
    const float* Whh0    = (const float*)d_in[7];
    const float* bih0    = (const float*)d_in[8];
    const float* bhh0    = (const float*)d_in[9];
    const float* Wih1    = (const float*)d_in[10];
    const float* Whh1    = (const float*)d_in[11];
    const float* bih1    = (const float*)d_in[12];
    const float* bhh1    = (const float*)d_in[13];
    const float* Wih2    = (const float*)d_in[14];
    const float* Whh2    = (const float*)d_in[15];
    const float* bih2    = (const float*)d_in[16];
    const float* bhh2    = (const float*)d_in[17];
    const float* W_proj  = (const float*)d_in[18];
    const float* b_proj  = (const float*)d_in[19];

    float* out = (float*)d_out;
    size_t logits_elems = (size_t)Bsz * Ssz * Vsz;
    float* pred = ((size_t)out_size >= logits_elems + (size_t)Bsz * Ssz)
                      ? out + logits_elems : nullptr;

    k_pack4<<<192, 256>>>(0, Whh0, 768, 256);
    k_pack4<<<96, 256>>>(1, Wih1, 384, 256);
    k_pack4<<<48, 256>>>(2, Whh1, 384, 128);
    k_pack4<<<12, 256>>>(3, Wih2, 96, 128);
    k_pack4<<<3, 256>>>(4, Whh2, 96, 32);
    k_pack4<<<384, 256>>>(5, Wih0, 768, 512);
    k_pack4<<<208, 256>>>(6, W_init, 416, 512);
    k_wproj<<<1, 256>>>(W_proj);
    k_g0<<<41, 768>>>(W_emb, b_emb, bih0);
    k_hinit<<<128, 416>>>(latent, b_init);
    k_main<<<NCTA, NTHR>>>(tokens, bhh0, bih1, bhh1, bih2, bhh2, b_proj, out, pred);
}

// round 2
// speedup vs baseline: 1.0005x; 1.0005x over previous
#include <cuda_runtime.h>
#include <math.h>

#define Bsz 1024
#define Ssz 350
#define Vsz 41
#define BT 8
#define NCTA 128
#define NTHR 256

typedef unsigned long long u64;

// ---------------- persistent device scratch ----------------
__device__ float4 g_A[49152];      // Whh0 e-pair packed: [kc][g][c2][j] -> {W[g*256+j][k],W[g*256+128+j][k],...k+1}
__device__ float4 g_B1rz[16384];   // Wih1 (r,z) pairs: [kc][c2][j]
__device__ float4 g_B1n[8192];     // Wih1 n rows: [kc][j] = 4 k
__device__ float4 g_B2rz[8192];    // Whh1 (r,z)
__device__ float4 g_B2n[4096];
__device__ float4 g_C1rz[2048];    // Wih2
__device__ float4 g_C1n[1024];
__device__ float4 g_C2rz[512];     // Whh2
__device__ float4 g_C2n[256];
__device__ float  g_WprojT[1312];  // [k][j]
__device__ float  g_G0x[41 * 768]; // [v][g][jm][e] pairs (u64-viewable)
__device__ float  g_Hinit[Bsz * 416];

// ---------------- f32x2 helpers ----------------
__device__ __forceinline__ u64 fma2(u64 a, u64 b, u64 c) {
    u64 d; asm("fma.rn.f32x2 %0,%1,%2,%3;" : "=l"(d) : "l"(a), "l"(b), "l"(c)); return d;
}
__device__ __forceinline__ u64 add2(u64 a, u64 b) {
    u64 d; asm("add.rn.f32x2 %0,%1,%2;" : "=l"(d) : "l"(a), "l"(b)); return d;
}
__device__ __forceinline__ u64 pk2(float x, float y) {
    u64 d; asm("mov.b64 %0,{%1,%2};" : "=l"(d) : "f"(x), "f"(y)); return d;
}
__device__ __forceinline__ void up2(u64 a, float& x, float& y) {
    asm("mov.b64 {%0,%1}, %2;" : "=f"(x), "=f"(y) : "l"(a));
}
__device__ __forceinline__ float lo2(u64 a) { float x, y; up2(a, x, y); return x; }

__device__ __forceinline__ float sigf(float x) {
    return __fdividef(1.0f, 1.0f + __expf(-x));
}
__device__ __forceinline__ float tanh_(float x) {
    float ax = fabsf(x);
    float e = __expf(-2.0f * ax);
    float t = __fdividef(1.0f - e, 1.0f + e);
    return copysignf(t, x);
}

// ---------------- fused prep kernel ----------------
// blocks 0..127: Hinit; 128..168: G0; 169..255: weight packing + WprojT
__global__ void k_prep(const float* __restrict__ latent, const float* __restrict__ W_emb,
                       const float* __restrict__ b_emb, const float* __restrict__ W_init,
                       const float* __restrict__ b_init, const float* __restrict__ Wih0,
                       const float* __restrict__ bih0, const float* __restrict__ Whh0,
                       const float* __restrict__ Wih1, const float* __restrict__ Whh1,
                       const float* __restrict__ Wih2, const float* __restrict__ Whh2,
                       const float* __restrict__ W_proj) {
    const int b = blockIdx.x, tid = threadIdx.x;
    if (b < 128) {
        // Hinit[row][c] = b_init[c] + latent[row] . W_init[c]
        __shared__ float lat[8 * 512];
        const int b0 = b * 8;
        for (int i = tid; i < 8 * 512; i += NTHR) lat[i] = latent[(size_t)b0 * 512 + i];
        __syncthreads();
        for (int c = tid; c < 416; c += NTHR) {
            float acc[8];
            float bi = b_init[c];
#pragma unroll
            for (int r = 0; r < 8; r++) acc[r] = bi;
            const float* w = W_init + (size_t)c * 512;
            for (int k = 0; k < 512; k += 4) {
                float4 wv = *(const float4*)(w + k);
#pragma unroll
                for (int r = 0; r < 8; r++) {
                    acc[r] += wv.x * lat[r * 512 + k];
                    acc[r] += wv.y * lat[r * 512 + k + 1];
                    acc[r] += wv.z * lat[r * 512 + k + 2];
                    acc[r] += wv.w * lat[r * 512 + k + 3];
                }
            }
#pragma unroll
            for (int r = 0; r < 8; r++) g_Hinit[(size_t)(b0 + r) * 416 + c] = acc[r];
        }
    } else if (b < 169) {
        // G0: v = b-128
        const int v = b - 128;
        __shared__ float emb[512];
        for (int k = tid; k < 512; k += NTHR) emb[k] = W_emb[k * Vsz + v] + b_emb[k];
        __syncthreads();
        for (int j = tid; j < 768; j += NTHR) {
            float acc = bih0[j];
            const float* w = Wih0 + (size_t)j * 512;
            for (int k = 0; k < 512; k += 4) {
                float4 wv = *(const float4*)(w + k);
                acc += wv.x * emb[k] + wv.y * emb[k + 1] + wv.z * emb[k + 2] + wv.w * emb[k + 3];
            }
            int g = j >> 8, rem = j & 255, e = rem >> 7, jm = rem & 127;
            g_G0x[(((size_t)v * 3 + g) * 128 + jm) * 2 + e] = acc;
        }
    } else {
        const int TOTAL = 90184;
        for (int i = (b - 169) * NTHR + tid; i < TOTAL; i += 87 * NTHR) {
            if (i < 49152) {  // A: Whh0
                int kc = i / 768, rem = i % 768;
                int g = rem / 256, rem2 = rem % 256, c2 = rem2 >> 7, jj = rem2 & 127;
                int k = 4 * kc + 2 * c2, row0 = g * 256 + jj, row1 = row0 + 128;
                g_A[i] = make_float4(Whh0[row0 * 256 + k], Whh0[row1 * 256 + k],
                                     Whh0[row0 * 256 + k + 1], Whh0[row1 * 256 + k + 1]);
            } else if (i < 65536) {  // B1rz
                int t = i - 49152;
                int kc = t / 256, c2 = (t & 255) >> 7, jj = t & 127, k = 4 * kc + 2 * c2;
                g_B1rz[t] = make_float4(Wih1[jj * 256 + k], Wih1[(128 + jj) * 256 + k],
                                        Wih1[jj * 256 + k + 1], Wih1[(128 + jj) * 256 + k + 1]);
            } else if (i < 73728) {  // B1n
                int t = i - 65536;
                int kc = t >> 7, jj = t & 127;
                g_B1n[t] = *(const float4*)&Wih1[(256 + jj) * 256 + 4 * kc];
            } else if (i < 81920) {  // B2rz
                int t = i - 73728;
                int kc = t / 256, c2 = (t & 255) >> 7, jj = t & 127, k = 4 * kc + 2 * c2;
                g_B2rz[t] = make_float4(Whh1[jj * 128 + k], Whh1[(128 + jj) * 128 + k],
                                        Whh1[jj * 128 + k + 1], Whh1[(128 + jj) * 128 + k + 1]);
            } else if (i < 86016) {  // B2n
                int t = i - 81920;
                int kc = t >> 7, jj = t & 127;
                g_B2n[t] = *(const float4*)&Whh1[(256 + jj) * 128 + 4 * kc];
            } else if (i < 88064) {  // C1rz
                int t = i - 86016;
                int kc = t / 64, c2 = (t & 63) >> 5, jc = t & 31, k = 4 * kc + 2 * c2;
                g_C1rz[t] = make_float4(Wih2[jc * 128 + k], Wih2[(32 + jc) * 128 + k],
                                        Wih2[jc * 128 + k + 1], Wih2[(32 + jc) * 128 + k + 1]);
            } else if (i < 89088) {  // C1n
                int t = i - 88064;
                int kc = t >> 5, jc = t & 31;
                g_C1n[t] = *(const float4*)&Wih2[(64 + jc) * 128 + 4 * kc];
            } else if (i < 89600) {  // C2rz
                int t = i - 89088;
                int kc = t / 64, c2 = (t & 63) >> 5, jc = t & 31, k = 4 * kc + 2 * c2;
                g_C2rz[t] = make_float4(Whh2[jc * 32 + k], Whh2[(32 + jc) * 32 + k],
                                        Whh2[jc * 32 + k + 1], Whh2[(32 + jc) * 32 + k + 1]);
            } else if (i < 89856) {  // C2n
                int t = i - 89600;
                int kc = t >> 5, jc = t & 31;
                g_C2n[t] = *(const float4*)&Whh2[(64 + jc) * 32 + 4 * kc];
            } else {  // WprojT
                int t2 = i - 89856;
#pragma unroll
                for (int c = 0; c < 4; c++) {
                    int e = t2 * 4 + c;
                    if (e < 1312) {
                        int k = e / Vsz, j = e - k * Vsz;
                        g_WprojT[e] = W_proj[j * 32 + k];
                    }
                }
            }
        }
    }
}

// ---------------- main persistent GRU kernel ----------------
__global__ __launch_bounds__(NTHR, 1)
void k_main(const int* __restrict__ tokens,
            const float* __restrict__ bhh0,
            const float* __restrict__ bih1, const float* __restrict__ bhh1,
            const float* __restrict__ bih2, const float* __restrict__ bhh2,
            const float* __restrict__ b_proj,
            float* __restrict__ out, float* __restrict__ pred) {
    // h stored DUPLICATED: h{L}d[k*8 + row] = (h,h) as u64
    __shared__ __align__(16) u64 h0d[256 * 8];
    __shared__ __align__(16) u64 h1d[128 * 8];
    __shared__ __align__(16) u64 h2d[32 * 8];
    __shared__ float lg[BT][44];
    __shared__ int toks_s[BT];

    const int tid = threadIdx.x;
    const int b0 = blockIdx.x * BT;
    const int jj = tid & 127;
    const int r0 = (tid >> 7) * 4;
    const int jc = tid & 31;
    const int rowC = tid >> 5;

    // initial state -> dup smem
    for (int idx = tid; idx < BT * 416; idx += NTHR) {
        int row = idx / 416, c = idx - row * 416;
        float v = g_Hinit[(size_t)(b0 + row) * 416 + c];
        if (c < 256)      h0d[c * 8 + row] = pk2(v, v);
        else if (c < 384) h1d[(c - 256) * 8 + row] = pk2(v, v);
        else              h2d[(c - 384) * 8 + row] = pk2(v, v);
    }

    // register-resident packed biases
    const u64 bA_r = pk2(bhh0[jj], bhh0[128 + jj]);
    const u64 bA_z = pk2(bhh0[256 + jj], bhh0[384 + jj]);
    const u64 bA_n = pk2(bhh0[512 + jj], bhh0[640 + jj]);
    const u64 bB_rz = pk2(bih1[jj] + bhh1[jj], bih1[128 + jj] + bhh1[128 + jj]);
    const float b1in = bih1[256 + jj], b1hn = bhh1[256 + jj];
    const u64 bB_in = pk2(b1in, b1in);
    const u64 bB_hn = pk2(b1hn, b1hn);
    const u64 bC_rz = pk2(bih2[jc] + bhh2[jc], bih2[32 + jc] + bhh2[32 + jc]);
    const float b2in = bih2[64 + jc], b2hn = bhh2[64 + jc];
    const u64 bC_in = pk2(b2in, b2in);
    const u64 bC_hn = pk2(b2hn, b2hn);

    const u64* __restrict__ G0p = (const u64*)g_G0x;

    __syncthreads();

    for (int st = 0; st < Ssz; st++) {
        if (tid < BT) toks_s[tid] = (st == 0) ? 1 : tokens[(size_t)(b0 + tid) * Ssz + st];
        __syncthreads();

        // ======== Phase A: layer 0 (e-pair packed) ========
        u64 aR[4], aZ[4], aN[4], gIN[4];
#pragma unroll
        for (int r = 0; r < 4; r++) {
            const u64* g = G0p + (size_t)toks_s[r0 + r] * 384;
            aR[r] = add2(g[jj], bA_r);
            aZ[r] = add2(g[128 + jj], bA_z);
            gIN[r] = g[256 + jj];
            aN[r] = bA_n;
        }
        for (int kc = 0; kc < 64; kc++) {
            const float4* base = g_A + kc * 768;
            ulonglong2 wr0 = *(const ulonglong2*)(base + jj);
            ulonglong2 wr1 = *(const ulonglong2*)(base + 128 + jj);
            ulonglong2 wz0 = *(const ulonglong2*)(base + 256 + jj);
            ulonglong2 wz1 = *(const ulonglong2*)(base + 384 + jj);
            ulonglong2 wn0 = *(const ulonglong2*)(base + 512 + jj);
            ulonglong2 wn1 = *(const ulonglong2*)(base + 640 + jj);
            u64 wR[4] = {wr0.x, wr0.y, wr1.x, wr1.y};
            u64 wZ[4] = {wz0.x, wz0.y, wz1.x, wz1.y};
            u64 wN[4] = {wn0.x, wn0.y, wn1.x, wn1.y};
            u64 hv[4][4];
#pragma unroll
            for (int c = 0; c < 4; c++) {
                ulonglong2 ha = *(const ulonglong2*)&h0d[(4 * kc + c) * 8 + r0];
                ulonglong2 hb = *(const ulonglong2*)&h0d[(4 * kc + c) * 8 + r0 + 2];
                hv[c][0] = ha.x; hv[c][1] = ha.y; hv[c][2] = hb.x; hv[c][3] = hb.y;
            }
#pragma unroll
            for (int c = 0; c < 4; c++)
#pragma unroll
                for (int r = 0; r < 4; r++) {
                    aR[r] = fma2(wR[c], hv[c][r], aR[r]);
                    aZ[r] = fma2(wZ[c], hv[c][r], aZ[r]);
                    aN[r] = fma2(wN[c], hv[c][r], aN[r]);
                }
        }
        __syncthreads();
#pragma unroll
        for (int r = 0; r < 4; r++) {
            float r0e, r1e, z0e, z1e, n0e, n1e, i0e, i1e;
            up2(aR[r], r0e, r1e); up2(aZ[r], z0e, z1e);
            up2(aN[r], n0e, n1e); up2(gIN[r], i0e, i1e);
            float hold0 = lo2(h0d[jj * 8 + r0 + r]);
            float hold1 = lo2(h0d[(128 + jj) * 8 + r0 + r]);
            float rg0 = sigf(r0e), rg1 = sigf(r1e);
            float zg0 = sigf(z0e), zg1 = sigf(z1e);
            float ng0 = tanh_(i0e + rg0 * n0e), ng1 = tanh_(i1e + rg1 * n1e);
            float v0 = (1.0f - zg0) * ng0 + zg0 * hold0;
            float v1 = (1.0f - zg1) * ng1 + zg1 * hold1;
            h0d[jj * 8 + r0 + r] = pk2(v0, v0);
            h0d[(128 + jj) * 8 + r0 + r] = pk2(v1, v1);
        }
        __syncthreads();

        // ======== Phase B: layer 1 (gate-pair packed) ========
        u64 rz[4], iN[4], hN[4];
#pragma unroll
        for (int r = 0; r < 4; r++) { rz[r] = bB_rz; iN[r] = bB_in; hN[r] = bB_hn; }
        for (int kc = 0; kc < 64; kc++) {
            const float4* brz = g_B1rz + kc * 256;
            ulonglong2 w01 = *(const ulonglong2*)(brz + jj);
            ulonglong2 w23 = *(const ulonglong2*)(brz + 128 + jj);
            float4 wn4 = g_B1n[kc * 128 + jj];
            u64 wrz[4] = {w01.x, w01.y, w23.x, w23.y};
            u64 wnd[4] = {pk2(wn4.x, wn4.x), pk2(wn4.y, wn4.y),
                          pk2(wn4.z, wn4.z), pk2(wn4.w, wn4.w)};
            u64 hv[4][4];
#pragma unroll
            for (int c = 0; c < 4; c++) {
                ulonglong2 ha = *(const ulonglong2*)&h0d[(4 * kc + c) * 8 + r0];
                ulonglong2 hb = *(const ulonglong2*)&h0d[(4 * kc + c) * 8 + r0 + 2];
                hv[c][0] = ha.x; hv[c][1] = ha.y; hv[c][2] = hb.x; hv[c][3] = hb.y;
            }
#pragma unroll
            for (int c = 0; c < 4; c++)
#pragma unroll
                for (int r = 0; r < 4; r++) {
                    rz[r] = fma2(wrz[c], hv[c][r], rz[r]);
                    iN[r] = fma2(wnd[c], hv[c][r], iN[r]);
                }
        }
        for (int kc = 0; kc < 32; kc++) {
            const float4* brz = g_B2rz + kc * 256;
            ulonglong2 w01 = *(const ulonglong2*)(brz + jj);
            ulonglong2 w23 = *(const ulonglong2*)(brz + 128 + jj);
            float4 wn4 = g_B2n[kc * 128 + jj];
            u64 wrz[4] = {w01.x, w01.y, w23.x, w23.y};
            u64 wnd[4] = {pk2(wn4.x, wn4.x), pk2(wn4.y, wn4.y),
                          pk2(wn4.z, wn4.z), pk2(wn4.w, wn4.w)};
            u64 hv[4][4];
#pragma unroll
            for (int c = 0; c < 4; c++) {
                ulonglong2 ha = *(const ulonglong2*)&h1d[(4 * kc + c) * 8 + r0];
                ulonglong2 hb = *(const ulonglong2*)&h1d[(4 * kc + c) * 8 + r0 + 2];
                hv[c][0] = ha.x; hv[c][1] = ha.y; hv[c][2] = hb.x; hv[c][3] = hb.y;
            }
#pragma unroll
            for (int c = 0; c < 4; c++)
#pragma unroll
                for (int r = 0; r < 4; r++) {
                    rz[r] = fma2(wrz[c], hv[c][r], rz[r]);
                    hN[r] = fma2(wnd[c], hv[c][r], hN[r]);
                }
        }
        __syncthreads();
#pragma unroll
        for (int r = 0; r < 4; r++) {
            float ar, az;
            up2(rz[r], ar, az);
            float hold = lo2(h1d[jj * 8 + r0 + r]);
            float rg = sigf(ar), zg = sigf(az);
            float ng = tanh_(lo2(iN[r]) + rg * lo2(hN[r]));
            float v = (1.0f - zg) * ng + zg * hold;
            h1d[jj * 8 + r0 + r] = pk2(v, v);
        }
        __syncthreads();

        // ======== Phase C: layer 2 ========
        u64 rz2 = bC_rz, iN2 = bC_in, hN2 = bC_hn;
        for (int kc = 0; kc < 32; kc++) {
            const float4* brz = g_C1rz + kc * 64;
            ulonglong2 w01 = *(const ulonglong2*)(brz + jc);
            ulonglong2 w23 = *(const ulonglong2*)(brz + 32 + jc);
            float4 wn4 = g_C1n[kc * 32 + jc];
            u64 wrz[4] = {w01.x, w01.y, w23.x, w23.y};
            u64 wnd[4] = {pk2(wn4.x, wn4.x), pk2(wn4.y, wn4.y),
                          pk2(wn4.z, wn4.z), pk2(wn4.w, wn4.w)};
#pragma unroll
            for (int c = 0; c < 4; c++) {
                u64 h = h1d[(4 * kc + c) * 8 + rowC];
                rz2 = fma2(wrz[c], h, rz2);
                iN2 = fma2(wnd[c], h, iN2);
            }
        }
        for (int kc = 0; kc < 8; kc++) {
            const float4* brz = g_C2rz + kc * 64;
            ulonglong2 w01 = *(const ulonglong2*)(brz + jc);
            ulonglong2 w23 = *(const ulonglong2*)(brz + 32 + jc);
            float4 wn4 = g_C2n[kc * 32 + jc];
            u64 wrz[4] = {w01.x, w01.y, w23.x, w23.y};
            u64 wnd[4] = {pk2(wn4.x, wn4.x), pk2(wn4.y, wn4.y),
                          pk2(wn4.z, wn4.z), pk2(wn4.w, wn4.w)};
#pragma unroll
            for (int c = 0; c < 4; c++) {
                u64 h = h2d[(4 * kc + c) * 8 + rowC];
                rz2 = fma2(wrz[c], h, rz2);
                hN2 = fma2(wnd[c], h, hN2);
            }
        }
        __syncthreads();
        {
            float cr, cz;
            up2(rz2, cr, cz);
            float hold = lo2(h2d[jc * 8 + rowC]);
            float rg = sigf(cr), zg = sigf(cz);
            float ng = tanh_(lo2(iN2) + rg * lo2(hN2));
            float v = (1.0f - zg) * ng + zg * hold;
            h2d[jc * 8 + rowC] = pk2(v, v);
        }
        __syncthreads();

        // ======== Phase D: projection + argmax ========
        for (int idx = tid; idx < BT * Vsz; idx += NTHR) {
            int row = idx / Vsz, j = idx - row * Vsz;
            float acc = b_proj[j];
#pragma unroll
            for (int k = 0; k < 32; k++)
                acc += g_WprojT[k * Vsz + j] * lo2(h2d[k * 8 + row]);
            out[((size_t)(b0 + row) * Ssz + st) * Vsz + j] = acc;
            lg[row][j] = acc;
        }
        __syncthreads();
        if (tid < BT && pred) {
            float best = lg[tid][0];
            int bi = 0;
#pragma unroll 1
            for (int j = 1; j < Vsz; j++) {
                float v = lg[tid][j];
                if (v > best) { best = v; bi = j; }
            }
            pred[(size_t)(b0 + tid) * Ssz + st] = (float)bi;
        }
        __syncthreads();
    }
}

// ---------------- launch ----------------
extern "C" void kernel_launch(void* const* d_in, const int* in_sizes, int n_in,
                              void* d_out, int out_size) {
    const float* latent  = (const float*)d_in[0];
    const int*   tokens  = (const int*)d_in[1];
    const float* W_emb   = (const float*)d_in[2];
    const float* b_emb   = (const float*)d_in[3];
    const float* W_init  = (const float*)d_in[4];
    const float* b_init  = (const float*)d_in[5];
    const float* Wih0    = (const float*)d_in[6];
    const float* Whh0    = (const float*)d_in[7];
    const float* bih0    = (const float*)d_in[8];
    const float* bhh0    = (const float*)d_in[9];
    const float* Wih1    = (const float*)d_in[10];
    const float* Whh1    = (const float*)d_in[11];
    const float* bih1    = (const float*)d_in[12];
    const float* bhh1    = (const float*)d_in[13];
    const float* Wih2    = (const float*)d_in[14];
    const float* Whh2    = (const float*)d_in[15];
    const float* bih2    = (const float*)d_in[16];
    const float* bhh2    = (const float*)d_in[17];
    const float* W_proj  = (const float*)d_in[18];
    const float* b_proj  = (const float*)d_in[19];

    float* out = (float*)d_out;
    size_t logits_elems = (size_t)Bsz * Ssz * Vsz;
    float* pred = ((size_t)out_size >= logits_elems + (size_t)Bsz * Ssz)
                      ? out + logits_elems : nullptr;

    k_prep<<<256, NTHR>>>(latent, W_emb, b_emb, W_init, b_init, Wih0, bih0, Whh0,
                          Wih1, Whh1, Wih2, Whh2, W_proj);
    k_main<<<NCTA, NTHR>>>(tokens, bhh0, bih1, bhh1, bih2, bhh2, b_proj, out, pred);
}